// round 5
// baseline (speedup 1.0000x reference)
#include <cuda_runtime.h>
#include <cstdint>
#include <math.h>

#define FULL 0xffffffffu

// ---------------------------------------------------------------------------
// Threefry-2x32 (20 rounds), matching jax._src.prng exactly.
// ---------------------------------------------------------------------------
__host__ __device__ __forceinline__ constexpr unsigned rotl_c(unsigned x, int r) {
    return (x << r) | (x >> (32 - r));
}

struct K2 { unsigned a, b; };

__host__ __device__ constexpr K2 tf_c(unsigned k0, unsigned k1, unsigned x0, unsigned x1) {
    unsigned ks2 = k0 ^ k1 ^ 0x1BD11BDAu;
    x0 += k0; x1 += k1;
    // rounds 1-4 (rot 13,15,26,6)
    x0 += x1; x1 = rotl_c(x1, 13); x1 ^= x0;
    x0 += x1; x1 = rotl_c(x1, 15); x1 ^= x0;
    x0 += x1; x1 = rotl_c(x1, 26); x1 ^= x0;
    x0 += x1; x1 = rotl_c(x1, 6);  x1 ^= x0;
    x0 += k1; x1 += ks2 + 1u;
    // rounds 5-8 (rot 17,29,16,24)
    x0 += x1; x1 = rotl_c(x1, 17); x1 ^= x0;
    x0 += x1; x1 = rotl_c(x1, 29); x1 ^= x0;
    x0 += x1; x1 = rotl_c(x1, 16); x1 ^= x0;
    x0 += x1; x1 = rotl_c(x1, 24); x1 ^= x0;
    x0 += ks2; x1 += k0 + 2u;
    // rounds 9-12
    x0 += x1; x1 = rotl_c(x1, 13); x1 ^= x0;
    x0 += x1; x1 = rotl_c(x1, 15); x1 ^= x0;
    x0 += x1; x1 = rotl_c(x1, 26); x1 ^= x0;
    x0 += x1; x1 = rotl_c(x1, 6);  x1 ^= x0;
    x0 += k0; x1 += k1 + 3u;
    // rounds 13-16
    x0 += x1; x1 = rotl_c(x1, 17); x1 ^= x0;
    x0 += x1; x1 = rotl_c(x1, 29); x1 ^= x0;
    x0 += x1; x1 = rotl_c(x1, 16); x1 ^= x0;
    x0 += x1; x1 = rotl_c(x1, 24); x1 ^= x0;
    x0 += k1; x1 += ks2 + 4u;
    // rounds 17-20
    x0 += x1; x1 = rotl_c(x1, 13); x1 ^= x0;
    x0 += x1; x1 = rotl_c(x1, 15); x1 ^= x0;
    x0 += x1; x1 = rotl_c(x1, 26); x1 ^= x0;
    x0 += x1; x1 = rotl_c(x1, 6);  x1 ^= x0;
    x0 += ks2; x1 += k0 + 5u;
    return K2{x0, x1};
}

// jax.random.key(42) -> key data [0, 42].
// Partitionable split: new key i = threefry(key, (0, i)) -> (out0, out1)
constexpr K2 KR = tf_c(0u, 42u, 0u, 0u);  // first split key  (used for rr)
constexpr K2 KG = tf_c(0u, 42u, 0u, 1u);  // second split key (used for gg)

// Partitionable random_bits(bit_width=32): 64-bit iota -> counts (0, f);
// bits = out0 ^ out1. Uniform f32 in [0,1): bitcast((bits>>9)|0x3f800000)-1.
__device__ __forceinline__ float tf_uniform(unsigned k0, unsigned k1, unsigned f) {
    K2 o = tf_c(k0, k1, 0u, f);
    unsigned bits = o.a ^ o.b;
    return __uint_as_float((bits >> 9) | 0x3f800000u) - 1.0f;
}

// ---------------------------------------------------------------------------
// XLA:CPU vectorized exp (GenerateVF32Exp / Cephes), WITH the backend's
// FPOpFusion::Fast contraction applied (x86 VFMADD/VFNMADD on every
// mul+add / sub-of-mul pair):
//   n  = floor(fma(a, log2e, 0.5))
//   x  = fma(-n, C1, a);  x = fma(-n, C2, x)        (Cody-Waite, fnmadd)
//   y  = fma(...Horner...);  y = fma(y, x*x, x);  y = y + 1
//   exp(a) = y * 2^n
// Clamp-free for |a| < ~87 (our inputs |p0| < ~6).
// ---------------------------------------------------------------------------
__device__ __forceinline__ float exp_xla_cpu_fma(float a) {
    const float kLog2e = 1.44269504088896341f;   // 0x3FB8AA3B
    const float kC1    = 0.693359375f;
    const float kC2    = -2.12194440e-4f;
    const float p0 = 1.9875691500E-4f;
    const float p1 = 1.3981999507E-3f;
    const float p2 = 8.3334519073E-3f;
    const float p3 = 4.1665795894E-2f;
    const float p4 = 1.6666665459E-1f;
    const float p5 = 5.0000001201E-1f;

    float n = floorf(fmaf(a, kLog2e, 0.5f));
    float x = fmaf(-n, kC1, a);        // vfnmadd: a - n*C1, single rounding
    x = fmaf(-n, kC2, x);              // x - n*C2, single rounding
    float z = __fmul_rn(x, x);
    float y = fmaf(x, p0, p1);
    y = fmaf(y, x, p2);
    y = fmaf(y, x, p3);
    y = fmaf(y, x, p4);
    y = fmaf(y, x, p5);
    y = fmaf(y, z, x);
    y = __fadd_rn(y, 1.0f);
    float pow2n = __int_as_float(((int)n + 127) << 23);
    return __fmul_rn(y, pow2n);
}

// XLA logistic_expander (exp form): 1 / (1 + exp(-x)), f32 IEEE steps.
__device__ __forceinline__ float logistic_f(float x) {
    float e = exp_xla_cpu_fma(-x);
    return __fdiv_rn(1.0f, __fadd_rn(1.0f, e));
}

// ---------------------------------------------------------------------------
constexpr float ONE_MINUS_EPS = (float)(1.0 - 1e-6);   // uniform * (1-EPSILON)
// IN_NUM=65536, OUT_NUM=65536, K=4, n=24, REGION=128, EMB=128

__global__ __launch_bounds__(256) void hyper_kernel(
    const float* __restrict__ params,
    const float* __restrict__ x,
    float* __restrict__ out)
{
    const int lane = threadIdx.x & 31;
    const int c = blockIdx.x * 8 + (threadIdx.x >> 5);   // one warp per output row

    // ---- per-k (lanes 0..3): mean, sigma, value -------------------------
    float mean = 0.f, sigma = 0.f, val = 0.f;
    if (lane < 4) {
        const float* pr = params + ((size_t)c * 4 + lane) * 3;
        float p0 = pr[0], p1 = pr[1], p2 = pr[2];
        mean = __fmul_rn(logistic_f(p0), 65535.0f);
        // softplus(p1 + 2) = max(z,0) + log1p(exp(-|z|))  (smooth; can't flip ints)
        float z = p1 + 2.0f;
        float sp = fmaxf(z, 0.0f) + log1pf(expf(-fabsf(z)));
        // ((sp + EPS) * in_num) * SIGMA_SCALE
        sigma = __fmul_rn(__fmul_rn(__fadd_rn(sp, 1e-6f), 65536.0f), 0.2f);
        val = p2;
    }
    float mk[4], sk[4], vk[4];
#pragma unroll
    for (int k = 0; k < 4; k++) {
        mk[k] = __shfl_sync(FULL, mean, k);
        sk[k] = __shfl_sync(FULL, sigma, k);
        vk[k] = __shfl_sync(FULL, val, k);
    }

    // ---- per-point (lanes 0..23): the integer index ---------------------
    int   myint = -1 - lane;   // unique negative sentinels for lanes 24..31
    float mypt = 0.f;
    if (lane < 24) {
        const int k = lane / 6;
        const int t = lane - k * 6;
        const float m = mk[k];
        float fv;
        if (t == 0) {
            fv = floorf(m);
        } else if (t == 1) {
            fv = ceilf(m);
        } else if (t < 4) {
            // region-random: rr = uniform * (1-eps); floor(rr*128 + lower)
            unsigned flat = (unsigned)c * 8u + (unsigned)k * 2u + (unsigned)(t - 2);
            float u  = tf_uniform(KR.a, KR.b, flat);
            float rr = __fmul_rn(u, ONE_MINUS_EPS);
            float mr = rintf(m);                  // jnp.round = half-to-even
            float lo = mr - 64.0f;
            float hi = mr + 64.0f;
            lo = (lo < 0.0f) ? 0.0f : lo;
            lo = (hi > 65536.0f) ? 65408.0f : lo; // in_num - REGION
            fv = floorf(__fadd_rn(__fmul_rn(rr, 128.0f), lo));
        } else {
            // global-random: floor((uniform * (1-eps)) * 65536)
            unsigned flat = (unsigned)c * 8u + (unsigned)k * 2u + (unsigned)(t - 4);
            float u = tf_uniform(KG.a, KG.b, flat);
            fv = floorf(__fmul_rn(__fmul_rn(u, ONE_MINUS_EPS), 65536.0f));
        }
        myint = (int)fv;
        mypt  = fv;
    }

    // ---- duplicate detection: dup iff some j' < j has equal int --------
    bool dup = false;
#pragma unroll
    for (int j = 0; j < 24; j++) {
        int oi = __shfl_sync(FULL, myint, j);
        if (j < lane && oi == myint) dup = true;
    }

    // ---- Gaussian props, normalize over the 24 points, mix values ------
    float v = 0.f;
    {
        float pk[4];
#pragma unroll
        for (int k = 0; k < 4; k++) {
            float d = mypt - mk[k];
            float e = __fmul_rn(__fmul_rn(-0.5f, d), d) / (1e-6f + sk[k]);
            float p = expf(e);
            pk[k] = (lane < 24 && !dup) ? p : 0.f;
        }
#pragma unroll
        for (int k = 0; k < 4; k++) {
            float s = pk[k];
#pragma unroll
            for (int off = 16; off; off >>= 1)
                s += __shfl_xor_sync(FULL, s, off);
            v += (pk[k] / s) * vk[k];
        }
    }
    if (myint == c) v = 0.f;   // rows == cols -> zero

    // ---- gather-weighted sum over x rows (L2-resident) -----------------
    const float4* __restrict__ x4 = (const float4*)x;
    float4 acc = make_float4(0.f, 0.f, 0.f, 0.f);
#pragma unroll
    for (int j = 0; j < 24; j++) {
        float vj = __shfl_sync(FULL, v, j);
        int   ij = __shfl_sync(FULL, myint, j);
        if (fabsf(vj) > 1e-12f) {   // dups/self/underflowed props contribute 0
            float4 q = __ldg(&x4[(size_t)ij * 32 + lane]);
            acc.x = fmaf(vj, q.x, acc.x);
            acc.y = fmaf(vj, q.y, acc.y);
            acc.z = fmaf(vj, q.z, acc.z);
            acc.w = fmaf(vj, q.w, acc.w);
        }
    }
    ((float4*)out)[(size_t)c * 32 + lane] = acc;
}

extern "C" void kernel_launch(void* const* d_in, const int* in_sizes, int n_in,
                              void* d_out, int out_size)
{
    const float* params = (const float*)d_in[0];   // (262144, 3) f32
    const float* x      = (const float*)d_in[1];   // (65536, 128) f32
    float* out          = (float*)d_out;           // (65536, 128) f32
    (void)in_sizes; (void)n_in; (void)out_size;
    hyper_kernel<<<65536 / 8, 256>>>(params, x, out);
}

// round 6
// speedup vs baseline: 1.4169x; 1.4169x over previous
#include <cuda_runtime.h>
#include <cstdint>
#include <math.h>

#define FULL 0xffffffffu

// ---------------------------------------------------------------------------
// Threefry-2x32 (20 rounds), matching jax._src.prng exactly.
// ---------------------------------------------------------------------------
__host__ __device__ __forceinline__ constexpr unsigned rotl_c(unsigned x, int r) {
    return (x << r) | (x >> (32 - r));
}

struct K2 { unsigned a, b; };

__host__ __device__ constexpr K2 tf_c(unsigned k0, unsigned k1, unsigned x0, unsigned x1) {
    unsigned ks2 = k0 ^ k1 ^ 0x1BD11BDAu;
    x0 += k0; x1 += k1;
    x0 += x1; x1 = rotl_c(x1, 13); x1 ^= x0;
    x0 += x1; x1 = rotl_c(x1, 15); x1 ^= x0;
    x0 += x1; x1 = rotl_c(x1, 26); x1 ^= x0;
    x0 += x1; x1 = rotl_c(x1, 6);  x1 ^= x0;
    x0 += k1; x1 += ks2 + 1u;
    x0 += x1; x1 = rotl_c(x1, 17); x1 ^= x0;
    x0 += x1; x1 = rotl_c(x1, 29); x1 ^= x0;
    x0 += x1; x1 = rotl_c(x1, 16); x1 ^= x0;
    x0 += x1; x1 = rotl_c(x1, 24); x1 ^= x0;
    x0 += ks2; x1 += k0 + 2u;
    x0 += x1; x1 = rotl_c(x1, 13); x1 ^= x0;
    x0 += x1; x1 = rotl_c(x1, 15); x1 ^= x0;
    x0 += x1; x1 = rotl_c(x1, 26); x1 ^= x0;
    x0 += x1; x1 = rotl_c(x1, 6);  x1 ^= x0;
    x0 += k0; x1 += k1 + 3u;
    x0 += x1; x1 = rotl_c(x1, 17); x1 ^= x0;
    x0 += x1; x1 = rotl_c(x1, 29); x1 ^= x0;
    x0 += x1; x1 = rotl_c(x1, 16); x1 ^= x0;
    x0 += x1; x1 = rotl_c(x1, 24); x1 ^= x0;
    x0 += k1; x1 += ks2 + 4u;
    x0 += x1; x1 = rotl_c(x1, 13); x1 ^= x0;
    x0 += x1; x1 = rotl_c(x1, 15); x1 ^= x0;
    x0 += x1; x1 = rotl_c(x1, 26); x1 ^= x0;
    x0 += x1; x1 = rotl_c(x1, 6);  x1 ^= x0;
    x0 += ks2; x1 += k0 + 5u;
    return K2{x0, x1};
}

// jax.random.key(42); partitionable split: key i = threefry(key, (0, i))
constexpr K2 KR = tf_c(0u, 42u, 0u, 0u);  // rr key
constexpr K2 KG = tf_c(0u, 42u, 0u, 1u);  // gg key

// Runtime threefry (uniform across warp; per-lane keys/counter).
__device__ __forceinline__ unsigned tf_bits(unsigned k0, unsigned k1, unsigned f) {
    K2 o = tf_c(k0, k1, 0u, f);
    return o.a ^ o.b;
}

// ---------------------------------------------------------------------------
// XLA:CPU vectorized exp (Cephes) WITH x86 FMA contraction (FPOpFusion::Fast).
// Boundary-critical: used ONLY for the sigmoid that positions the means.
// ---------------------------------------------------------------------------
__device__ __forceinline__ float exp_xla_cpu_fma(float a) {
    const float kLog2e = 1.44269504088896341f;
    const float kC1    = 0.693359375f;
    const float kC2    = -2.12194440e-4f;
    float n = floorf(fmaf(a, kLog2e, 0.5f));
    float x = fmaf(-n, kC1, a);
    x = fmaf(-n, kC2, x);
    float z = __fmul_rn(x, x);
    float y = fmaf(x, 1.9875691500E-4f, 1.3981999507E-3f);
    y = fmaf(y, x, 8.3334519073E-3f);
    y = fmaf(y, x, 4.1665795894E-2f);
    y = fmaf(y, x, 1.6666665459E-1f);
    y = fmaf(y, x, 5.0000001201E-1f);
    y = fmaf(y, z, x);
    y = __fadd_rn(y, 1.0f);
    float pow2n = __int_as_float(((int)n + 127) << 23);
    return __fmul_rn(y, pow2n);
}

__device__ __forceinline__ float logistic_f(float x) {
    float e = exp_xla_cpu_fma(-x);
    return __fdiv_rn(1.0f, __fadd_rn(1.0f, e));
}

constexpr float ONE_MINUS_EPS = (float)(1.0 - 1e-6);
// IN_NUM=65536, OUT_NUM=65536, K=4, n=24, REGION=128, EMB=128

__global__ __launch_bounds__(256) void hyper_kernel(
    const float* __restrict__ params,
    const float* __restrict__ x,
    float* __restrict__ out)
{
    const int lane = threadIdx.x & 31;
    const int c = blockIdx.x * 8 + (threadIdx.x >> 5);   // one warp per row

    // ---- per-k (lanes 0..3): mean (EXACT path), sigma-reciprocal, value ----
    float mean = 0.f, rinv = 0.f, val = 0.f;
    if (lane < 4) {
        const float* pr = params + ((size_t)c * 4 + lane) * 3;
        float p0 = pr[0], p1 = pr[1], p2 = pr[2];
        mean = __fmul_rn(logistic_f(p0), 65535.0f);
        // softplus (smooth path — cannot flip integers)
        float z = p1 + 2.0f;
        float sp = fmaxf(z, 0.0f) + log1pf(expf(-fabsf(z)));
        float sigma = __fmul_rn(__fmul_rn(__fadd_rn(sp, 1e-6f), 65536.0f), 0.2f);
        rinv = __fdividef(-0.5f, 1e-6f + sigma);   // premultiplied -0.5/(eps+sig)
        val = p2;
    }
    float mk[4], rk[4], vk[4];
#pragma unroll
    for (int k = 0; k < 4; k++) {
        mk[k] = __shfl_sync(FULL, mean, k);
        rk[k] = __shfl_sync(FULL, rinv, k);
        vk[k] = __shfl_sync(FULL, val, k);
    }

    // ---- per-point (lane j): UNIFIED single threefry for all lanes --------
    const int k6 = lane / 6;                 // 4..5 for lanes>=24 (discarded)
    const int t  = lane - k6 * 6;
    const float m = __shfl_sync(FULL, mean, k6);   // lanes>=24 read 0

    const bool isg = (t >= 4);
    unsigned key0 = isg ? KG.a : KR.a;
    unsigned key1 = isg ? KG.b : KR.b;
    unsigned flat = (unsigned)c * 8u + (unsigned)k6 * 2u + (unsigned)(t & 1);
    unsigned bits = tf_bits(key0, key1, flat);
    float u  = __uint_as_float((bits >> 9) | 0x3f800000u) - 1.0f;
    float rr = __fmul_rn(u, ONE_MINUS_EPS);

    // region bounds (exact per reference)
    float mr = rintf(m);
    float lo = mr - 64.0f;
    float hi = mr + 64.0f;
    lo = (lo < 0.0f) ? 0.0f : lo;
    lo = (hi > 65536.0f) ? 65408.0f : lo;

    float fv = (t == 0) ? floorf(m)
             : (t == 1) ? ceilf(m)
             : (t <  4) ? floorf(__fadd_rn(__fmul_rn(rr, 128.0f), lo))
                        : floorf(__fmul_rn(rr, 65536.0f));
    const int myint = (lane < 24) ? (int)fv : (-1 - lane);  // unique sentinels
    const float mypt = fv;

    // ---- duplicate detection in ONE instruction ---------------------------
    unsigned mmask = __match_any_sync(FULL, myint);
    const bool dup = (mmask & ((1u << lane) - 1u)) != 0u;
    const bool act0 = (lane < 24) && !dup;

    // ---- Gaussian props, normalize, mix ------------------------------------
    float v = 0.f;
    float pk[4];
#pragma unroll
    for (int k = 0; k < 4; k++) {
        float d = mypt - mk[k];
        float e = __fmul_rn(__fmul_rn(d, d), rk[k]);
        pk[k] = act0 ? __expf(e) : 0.f;
    }
#pragma unroll
    for (int k = 0; k < 4; k++) {
        float s = pk[k];
#pragma unroll
        for (int off = 16; off; off >>= 1)
            s += __shfl_xor_sync(FULL, s, off);
        float w = __fdividef(vk[k], s);     // fast div; smooth path
        v = fmaf(pk[k], w, v);
    }
    if (myint == c) v = 0.f;                // rows == cols -> zero

    // ---- gather-weighted sum (L2-resident x), dual accumulators -----------
    const float4* __restrict__ xb = (const float4*)x + lane;
    float4 a0 = make_float4(0.f, 0.f, 0.f, 0.f);
    float4 a1 = make_float4(0.f, 0.f, 0.f, 0.f);
#pragma unroll
    for (int j = 0; j < 24; j += 2) {
        float v0 = __shfl_sync(FULL, v, j);
        int   i0 = __shfl_sync(FULL, myint, j);
        float v1 = __shfl_sync(FULL, v, j + 1);
        int   i1 = __shfl_sync(FULL, myint, j + 1);
        if (fabsf(v0) > 1e-12f) {
            float4 q = __ldg(xb + ((unsigned)i0 << 5));
            a0.x = fmaf(v0, q.x, a0.x);
            a0.y = fmaf(v0, q.y, a0.y);
            a0.z = fmaf(v0, q.z, a0.z);
            a0.w = fmaf(v0, q.w, a0.w);
        }
        if (fabsf(v1) > 1e-12f) {
            float4 q = __ldg(xb + ((unsigned)i1 << 5));
            a1.x = fmaf(v1, q.x, a1.x);
            a1.y = fmaf(v1, q.y, a1.y);
            a1.z = fmaf(v1, q.z, a1.z);
            a1.w = fmaf(v1, q.w, a1.w);
        }
    }
    a0.x += a1.x; a0.y += a1.y; a0.z += a1.z; a0.w += a1.w;
    ((float4*)out)[(size_t)c * 32 + lane] = a0;
}

extern "C" void kernel_launch(void* const* d_in, const int* in_sizes, int n_in,
                              void* d_out, int out_size)
{
    const float* params = (const float*)d_in[0];   // (262144, 3) f32
    const float* x      = (const float*)d_in[1];   // (65536, 128) f32
    float* out          = (float*)d_out;           // (65536, 128) f32
    (void)in_sizes; (void)n_in; (void)out_size;
    hyper_kernel<<<65536 / 8, 256>>>(params, x, out);
}

// round 7
// speedup vs baseline: 1.4354x; 1.0131x over previous
#include <cuda_runtime.h>
#include <cstdint>
#include <math.h>

#define FULL 0xffffffffu

// ---------------------------------------------------------------------------
// Threefry-2x32 (20 rounds), matching jax._src.prng exactly.
// ---------------------------------------------------------------------------
__host__ __device__ __forceinline__ constexpr unsigned rotl_c(unsigned x, int r) {
    return (x << r) | (x >> (32 - r));
}

struct K2 { unsigned a, b; };

__host__ __device__ constexpr K2 tf_c(unsigned k0, unsigned k1, unsigned x0, unsigned x1) {
    unsigned ks2 = k0 ^ k1 ^ 0x1BD11BDAu;
    x0 += k0; x1 += k1;
    x0 += x1; x1 = rotl_c(x1, 13); x1 ^= x0;
    x0 += x1; x1 = rotl_c(x1, 15); x1 ^= x0;
    x0 += x1; x1 = rotl_c(x1, 26); x1 ^= x0;
    x0 += x1; x1 = rotl_c(x1, 6);  x1 ^= x0;
    x0 += k1; x1 += ks2 + 1u;
    x0 += x1; x1 = rotl_c(x1, 17); x1 ^= x0;
    x0 += x1; x1 = rotl_c(x1, 29); x1 ^= x0;
    x0 += x1; x1 = rotl_c(x1, 16); x1 ^= x0;
    x0 += x1; x1 = rotl_c(x1, 24); x1 ^= x0;
    x0 += ks2; x1 += k0 + 2u;
    x0 += x1; x1 = rotl_c(x1, 13); x1 ^= x0;
    x0 += x1; x1 = rotl_c(x1, 15); x1 ^= x0;
    x0 += x1; x1 = rotl_c(x1, 26); x1 ^= x0;
    x0 += x1; x1 = rotl_c(x1, 6);  x1 ^= x0;
    x0 += k0; x1 += k1 + 3u;
    x0 += x1; x1 = rotl_c(x1, 17); x1 ^= x0;
    x0 += x1; x1 = rotl_c(x1, 29); x1 ^= x0;
    x0 += x1; x1 = rotl_c(x1, 16); x1 ^= x0;
    x0 += x1; x1 = rotl_c(x1, 24); x1 ^= x0;
    x0 += k1; x1 += ks2 + 4u;
    x0 += x1; x1 = rotl_c(x1, 13); x1 ^= x0;
    x0 += x1; x1 = rotl_c(x1, 15); x1 ^= x0;
    x0 += x1; x1 = rotl_c(x1, 26); x1 ^= x0;
    x0 += x1; x1 = rotl_c(x1, 6);  x1 ^= x0;
    x0 += ks2; x1 += k0 + 5u;
    return K2{x0, x1};
}

// jax.random.key(42); partitionable split: key i = threefry(key, (0, i))
constexpr K2 KR = tf_c(0u, 42u, 0u, 0u);  // rr key
constexpr K2 KG = tf_c(0u, 42u, 0u, 1u);  // gg key

__device__ __forceinline__ unsigned tf_bits(unsigned k0, unsigned k1, unsigned f) {
    K2 o = tf_c(k0, k1, 0u, f);
    return o.a ^ o.b;
}

// ---------------------------------------------------------------------------
// XLA:CPU vectorized exp (Cephes) WITH x86 FMA contraction (FPOpFusion::Fast).
// Boundary-critical: used ONLY for the sigmoid that positions the means.
// ---------------------------------------------------------------------------
__device__ __forceinline__ float exp_xla_cpu_fma(float a) {
    const float kLog2e = 1.44269504088896341f;
    const float kC1    = 0.693359375f;
    const float kC2    = -2.12194440e-4f;
    float n = floorf(fmaf(a, kLog2e, 0.5f));
    float x = fmaf(-n, kC1, a);
    x = fmaf(-n, kC2, x);
    float z = __fmul_rn(x, x);
    float y = fmaf(x, 1.9875691500E-4f, 1.3981999507E-3f);
    y = fmaf(y, x, 8.3334519073E-3f);
    y = fmaf(y, x, 4.1665795894E-2f);
    y = fmaf(y, x, 1.6666665459E-1f);
    y = fmaf(y, x, 5.0000001201E-1f);
    y = fmaf(y, z, x);
    y = __fadd_rn(y, 1.0f);
    float pow2n = __int_as_float(((int)n + 127) << 23);
    return __fmul_rn(y, pow2n);
}

__device__ __forceinline__ float logistic_f(float x) {
    float e = exp_xla_cpu_fma(-x);
    return __fdiv_rn(1.0f, __fadd_rn(1.0f, e));
}

constexpr float ONE_MINUS_EPS = (float)(1.0 - 1e-6);
// IN_NUM=65536, OUT_NUM=65536, K=4, n=24, REGION=128, EMB=128

__global__ __launch_bounds__(256) void hyper_kernel(
    const float* __restrict__ params,
    const float* __restrict__ x,
    float* __restrict__ out)
{
    const int lane = threadIdx.x & 31;
    const int c = blockIdx.x * 8 + (threadIdx.x >> 5);   // one warp per row

    // ---- per-k (lanes 0..3): mean (EXACT path), sigma-reciprocal, value ----
    float mean = 0.f, rinv = 0.f, val = 0.f;
    if (lane < 4) {
        const float* pr = params + ((size_t)c * 4 + lane) * 3;
        float p0 = pr[0], p1 = pr[1], p2 = pr[2];
        mean = __fmul_rn(logistic_f(p0), 65535.0f);
        // softplus (smooth path — cannot flip integers)
        float z = p1 + 2.0f;
        float sp = fmaxf(z, 0.0f) + log1pf(expf(-fabsf(z)));
        float sigma = __fmul_rn(__fmul_rn(__fadd_rn(sp, 1e-6f), 65536.0f), 0.2f);
        rinv = __fdividef(-0.5f, 1e-6f + sigma);   // premultiplied -0.5/(eps+sig)
        val = p2;
    }
    float mk[4], rk[4], vk[4];
#pragma unroll
    for (int k = 0; k < 4; k++) {
        mk[k] = __shfl_sync(FULL, mean, k);
        rk[k] = __shfl_sync(FULL, rinv, k);
        vk[k] = __shfl_sync(FULL, val, k);
    }

    // ---- per-point (lane j): unified single threefry ----------------------
    const int k6 = lane / 6;                 // 4..5 for lanes>=24 (discarded)
    const int t  = lane - k6 * 6;
    const float m = __shfl_sync(FULL, mean, k6);   // lanes>=24 read 0

    const bool isg = (t >= 4);
    unsigned key0 = isg ? KG.a : KR.a;
    unsigned key1 = isg ? KG.b : KR.b;
    unsigned flat = (unsigned)c * 8u + (unsigned)k6 * 2u + (unsigned)(t & 1);
    unsigned bits = tf_bits(key0, key1, flat);
    float u  = __uint_as_float((bits >> 9) | 0x3f800000u) - 1.0f;
    float rr = __fmul_rn(u, ONE_MINUS_EPS);

    // region bounds (exact per reference)
    float mr = rintf(m);
    float lo = mr - 64.0f;
    float hi = mr + 64.0f;
    lo = (lo < 0.0f) ? 0.0f : lo;
    lo = (hi > 65536.0f) ? 65408.0f : lo;

    float fv = (t == 0) ? floorf(m)
             : (t == 1) ? ceilf(m)
             : (t <  4) ? floorf(__fadd_rn(__fmul_rn(rr, 128.0f), lo))
                        : floorf(__fmul_rn(rr, 65536.0f));
    const int myint = (lane < 24) ? (int)fv : (-1 - lane);  // unique sentinels
    const float mypt = fv;

    // ---- duplicate detection in one instruction ---------------------------
    unsigned mmask = __match_any_sync(FULL, myint);
    const bool dup = (mmask & ((1u << lane) - 1u)) != 0u;
    const bool act0 = (lane < 24) && !dup;

    // ---- Gaussian props, normalize, mix ------------------------------------
    float v = 0.f;
    float pk[4];
#pragma unroll
    for (int k = 0; k < 4; k++) {
        float d = mypt - mk[k];
        float e = __fmul_rn(__fmul_rn(d, d), rk[k]);
        pk[k] = act0 ? __expf(e) : 0.f;
    }
#pragma unroll
    for (int k = 0; k < 4; k++) {
        float s = pk[k];
#pragma unroll
        for (int off = 16; off; off >>= 1)
            s += __shfl_xor_sync(FULL, s, off);
        float w = __fdividef(vk[k], s);     // fast div; smooth path
        v = fmaf(pk[k], w, v);
    }
    if (myint == c) v = 0.f;                // rows == cols -> zero

    // ---- ballot-compacted gather: only active points issue loads ----------
    unsigned amask = __ballot_sync(FULL, fabsf(v) > 1e-12f);
    const float4* __restrict__ xb = (const float4*)x + lane;
    float4 a0 = make_float4(0.f, 0.f, 0.f, 0.f);
    float4 a1 = make_float4(0.f, 0.f, 0.f, 0.f);
    while (amask) {
        int s0 = __ffs(amask) - 1;
        amask &= amask - 1u;
        float v0 = __shfl_sync(FULL, v, s0);
        int   i0 = __shfl_sync(FULL, myint, s0);
        if (amask) {
            int s1 = __ffs(amask) - 1;
            amask &= amask - 1u;
            float v1 = __shfl_sync(FULL, v, s1);
            int   i1 = __shfl_sync(FULL, myint, s1);
            float4 q0 = __ldg(xb + ((unsigned)i0 << 5));
            float4 q1 = __ldg(xb + ((unsigned)i1 << 5));
            a0.x = fmaf(v0, q0.x, a0.x);
            a0.y = fmaf(v0, q0.y, a0.y);
            a0.z = fmaf(v0, q0.z, a0.z);
            a0.w = fmaf(v0, q0.w, a0.w);
            a1.x = fmaf(v1, q1.x, a1.x);
            a1.y = fmaf(v1, q1.y, a1.y);
            a1.z = fmaf(v1, q1.z, a1.z);
            a1.w = fmaf(v1, q1.w, a1.w);
        } else {
            float4 q0 = __ldg(xb + ((unsigned)i0 << 5));
            a0.x = fmaf(v0, q0.x, a0.x);
            a0.y = fmaf(v0, q0.y, a0.y);
            a0.z = fmaf(v0, q0.z, a0.z);
            a0.w = fmaf(v0, q0.w, a0.w);
        }
    }
    a0.x += a1.x; a0.y += a1.y; a0.z += a1.z; a0.w += a1.w;
    ((float4*)out)[(unsigned)c * 32u + (unsigned)lane] = a0;
}

extern "C" void kernel_launch(void* const* d_in, const int* in_sizes, int n_in,
                              void* d_out, int out_size)
{
    const float* params = (const float*)d_in[0];   // (262144, 3) f32
    const float* x      = (const float*)d_in[1];   // (65536, 128) f32
    float* out          = (float*)d_out;           // (65536, 128) f32
    (void)in_sizes; (void)n_in; (void)out_size;
    hyper_kernel<<<65536 / 8, 256>>>(params, x, out);
}